// round 12
// baseline (speedup 1.0000x reference)
#include <cuda_runtime.h>

// out[i] = cos(x[i,0] + w0), x: [N,2] float32 interleaved, N = 16777216 (2^24).
// Purely DRAM-bound (issue=12.7% in R11). R12: persistent single-wave grid —
// 1184 CTAs (148 SMs x 8) with a warp-contiguous grid-stride loop, eliminating
// ~6 wave transitions of the 8192-CTA launch. Per iteration each warp handles
// 128 consecutive float4s (MLP=4 coalesced 512B loads), __cosf, streaming stores.

__global__ void __launch_bounds__(256)
hybrid_qnn_cos_kernel(const float4* __restrict__ x4,   // N/2 float4s (each = 2 samples)
                      const float* __restrict__ w,
                      float2* __restrict__ out2,       // N/2 float2s
                      int n_x4)                         // N/2
{
    const float w0 = __ldg(w);

    int lane = threadIdx.x & 31;
    int warp_global = (blockIdx.x * blockDim.x + threadIdx.x) >> 5;
    int n_warps = (gridDim.x * blockDim.x) >> 5;

    size_t warp_span = 128;                         // float4s per warp-iteration
    size_t stride = (size_t)n_warps * warp_span;    // global stride per iteration

    for (size_t base = (size_t)warp_global * warp_span + lane;
         base + 96 < (size_t)n_x4 + 1;              // full tiles only (N/2 divisible)
         base += stride)
    {
        float4 a = __ldg(x4 + base);
        float4 b = __ldg(x4 + base + 32);
        float4 c = __ldg(x4 + base + 64);
        float4 d = __ldg(x4 + base + 96);

        float2 oa = make_float2(__cosf(a.x + w0), __cosf(a.z + w0));
        float2 ob = make_float2(__cosf(b.x + w0), __cosf(b.z + w0));
        float2 oc = make_float2(__cosf(c.x + w0), __cosf(c.z + w0));
        float2 od = make_float2(__cosf(d.x + w0), __cosf(d.z + w0));

        __stcs(out2 + base,      oa);
        __stcs(out2 + base + 32, ob);
        __stcs(out2 + base + 64, oc);
        __stcs(out2 + base + 96, od);
    }
}

extern "C" void kernel_launch(void* const* d_in, const int* in_sizes, int n_in,
                              void* d_out, int out_size)
{
    const float4* x4 = (const float4*)d_in[0];   // x: [N,2] float32
    const float*  w  = (const float*)d_in[1];    // weights: [2] float32
    float2* out2 = (float2*)d_out;

    int n = in_sizes[0] / 2;        // N samples (2^24)
    int n_x4 = n / 2;               // float4s in x (2^23)

    // Persistent single wave: 148 SMs x 8 CTAs of 256 threads.
    const int threads = 256;
    const int blocks = 148 * 8;     // 1184 CTAs, 9472 warps, ~6.9 iters/warp

    hybrid_qnn_cos_kernel<<<blocks, threads>>>(x4, w, out2, n_x4);
}

// round 13
// speedup vs baseline: 1.0010x; 1.0010x over previous
#include <cuda_runtime.h>

// out[i] = cos(x[i,0] + w0), x: [N,2] float32 interleaved, N = 16777216 (2^24).
// Purely DRAM-bound (R11: issue=12.7%, DRAM=77.8%). R13 = R11 structure with
// 512-thread blocks (identical warp->data mapping, half the CTA count):
// warp-contiguous MLP=4 — each warp owns 128 consecutive float4s, every LDG.128
// perfectly coalesced (512B), __cosf, 4 coalesced float2 streaming stores.

__global__ void __launch_bounds__(512)
hybrid_qnn_cos_kernel(const float4* __restrict__ x4,   // N/2 float4s (each = 2 samples)
                      const float* __restrict__ w,
                      float2* __restrict__ out2)       // N/2 float2s
{
    const float w0 = __ldg(w);

    int t = blockIdx.x * blockDim.x + threadIdx.x;
    int warp = t >> 5;
    int lane = t & 31;
    size_t base = (size_t)warp * 128 + lane;

    // 4 independent, warp-coalesced 128B loads (MLP=4, 4 lines per instruction).
    float4 a = __ldg(x4 + base);
    float4 b = __ldg(x4 + base + 32);
    float4 c = __ldg(x4 + base + 64);
    float4 d = __ldg(x4 + base + 96);

    float2 oa = make_float2(__cosf(a.x + w0), __cosf(a.z + w0));
    float2 ob = make_float2(__cosf(b.x + w0), __cosf(b.z + w0));
    float2 oc = make_float2(__cosf(c.x + w0), __cosf(c.z + w0));
    float2 od = make_float2(__cosf(d.x + w0), __cosf(d.z + w0));

    // 4 warp-coalesced 256B streaming stores.
    __stcs(out2 + base,      oa);
    __stcs(out2 + base + 32, ob);
    __stcs(out2 + base + 64, oc);
    __stcs(out2 + base + 96, od);
}

extern "C" void kernel_launch(void* const* d_in, const int* in_sizes, int n_in,
                              void* d_out, int out_size)
{
    const float4* x4 = (const float4*)d_in[0];   // x: [N,2] float32
    const float*  w  = (const float*)d_in[1];    // weights: [2] float32
    float2* out2 = (float2*)d_out;

    int n = in_sizes[0] / 2;        // N samples (2^24)
    int n_x4 = n / 2;               // float4s in x (2^23)
    int n_thread = n_x4 / 4;        // 4 float4s (8 samples) per thread (2^21)

    const int threads = 512;
    int blocks = n_thread / threads;   // 4096 blocks, exact

    hybrid_qnn_cos_kernel<<<blocks, threads>>>(x4, w, out2);
}

// round 14
// speedup vs baseline: 1.0234x; 1.0225x over previous
#include <cuda_runtime.h>

// out[i] = cos(x[i,0] + w0), x: [N,2] float32 interleaved, N = 16777216 (2^24).
// At the DRAM wall (R13: DRAM=78.3%, issue=13.2%, 26.0us kernel). R14 = R13 with
// plain writeback stores (drop .cs) — last single-variable probe on the store path.
// Warp-contiguous MLP=4: each warp owns 128 consecutive float4s, every LDG.128
// perfectly coalesced (512B/instr), __cosf (MUFU), 4 coalesced float2 stores.

__global__ void __launch_bounds__(512)
hybrid_qnn_cos_kernel(const float4* __restrict__ x4,   // N/2 float4s (each = 2 samples)
                      const float* __restrict__ w,
                      float2* __restrict__ out2)       // N/2 float2s
{
    const float w0 = __ldg(w);

    int t = blockIdx.x * blockDim.x + threadIdx.x;
    int warp = t >> 5;
    int lane = t & 31;
    size_t base = (size_t)warp * 128 + lane;

    // 4 independent, warp-coalesced 128B loads (MLP=4, 4 lines per instruction).
    float4 a = __ldg(x4 + base);
    float4 b = __ldg(x4 + base + 32);
    float4 c = __ldg(x4 + base + 64);
    float4 d = __ldg(x4 + base + 96);

    float2 oa = make_float2(__cosf(a.x + w0), __cosf(a.z + w0));
    float2 ob = make_float2(__cosf(b.x + w0), __cosf(b.z + w0));
    float2 oc = make_float2(__cosf(c.x + w0), __cosf(c.z + w0));
    float2 od = make_float2(__cosf(d.x + w0), __cosf(d.z + w0));

    // 4 warp-coalesced 256B writeback stores.
    out2[base]      = oa;
    out2[base + 32] = ob;
    out2[base + 64] = oc;
    out2[base + 96] = od;
}

extern "C" void kernel_launch(void* const* d_in, const int* in_sizes, int n_in,
                              void* d_out, int out_size)
{
    const float4* x4 = (const float4*)d_in[0];   // x: [N,2] float32
    const float*  w  = (const float*)d_in[1];    // weights: [2] float32
    float2* out2 = (float2*)d_out;

    int n = in_sizes[0] / 2;        // N samples (2^24)
    int n_x4 = n / 2;               // float4s in x (2^23)
    int n_thread = n_x4 / 4;        // 4 float4s (8 samples) per thread (2^21)

    const int threads = 512;
    int blocks = n_thread / threads;   // 4096 blocks, exact

    hybrid_qnn_cos_kernel<<<blocks, threads>>>(x4, w, out2);
}

// round 15
// speedup vs baseline: 1.0738x; 1.0492x over previous
#include <cuda_runtime.h>

// out[i] = cos(x[i,0] + w0), x: [N,2] float32 interleaved, N = 16777216 (2^24).
// FINAL (R11, best measured): purely DRAM-bound at ~6.2-6.3 TB/s (78-79% of spec),
// issue=13% — at the mixed-stream HBM wall for a 192MB one-touch kernel.
// Structure: warp-contiguous MLP=4 — each warp owns 128 consecutive float4s, so
// every LDG.128 is a perfectly coalesced 512B/4-line wavefront group (halves
// L1tex wavefronts vs thread-contiguous); __cosf (MUFU) keeps the dependency
// chain ~2 ops (rel_err 1.3e-7, well under 1e-3); 4 coalesced float2 streaming
// stores. Exact grid 8192x256.
//
// Axes probed and closed: MLP 2/4/8 (4 best), .cs loads (sector-split pathology,
// -30%), L2 evict_last pinning full/partial (no cross-replay retention),
// persistent single-wave grid (-5%), block 512 (neutral), 32B loads (neutral),
// plain stores (neutral).

__global__ void __launch_bounds__(256)
hybrid_qnn_cos_kernel(const float4* __restrict__ x4,   // N/2 float4s (each = 2 samples)
                      const float* __restrict__ w,
                      float2* __restrict__ out2)       // N/2 float2s
{
    const float w0 = __ldg(w);

    int t = blockIdx.x * blockDim.x + threadIdx.x;
    int warp = t >> 5;
    int lane = t & 31;
    size_t base = (size_t)warp * 128 + lane;

    // 4 independent, warp-coalesced 128B loads (MLP=4, 4 lines per instruction).
    float4 a = __ldg(x4 + base);
    float4 b = __ldg(x4 + base + 32);
    float4 c = __ldg(x4 + base + 64);
    float4 d = __ldg(x4 + base + 96);

    float2 oa = make_float2(__cosf(a.x + w0), __cosf(a.z + w0));
    float2 ob = make_float2(__cosf(b.x + w0), __cosf(b.z + w0));
    float2 oc = make_float2(__cosf(c.x + w0), __cosf(c.z + w0));
    float2 od = make_float2(__cosf(d.x + w0), __cosf(d.z + w0));

    // 4 warp-coalesced 256B streaming stores.
    __stcs(out2 + base,      oa);
    __stcs(out2 + base + 32, ob);
    __stcs(out2 + base + 64, oc);
    __stcs(out2 + base + 96, od);
}

extern "C" void kernel_launch(void* const* d_in, const int* in_sizes, int n_in,
                              void* d_out, int out_size)
{
    const float4* x4 = (const float4*)d_in[0];   // x: [N,2] float32
    const float*  w  = (const float*)d_in[1];    // weights: [2] float32
    float2* out2 = (float2*)d_out;

    int n = in_sizes[0] / 2;        // N samples (2^24)
    int n_x4 = n / 2;               // float4s in x (2^23)
    int n_thread = n_x4 / 4;        // 4 float4s (8 samples) per thread (2^21)

    const int threads = 256;
    int blocks = n_thread / threads;   // 8192 blocks, exact

    hybrid_qnn_cos_kernel<<<blocks, threads>>>(x4, w, out2);
}

// round 16
// speedup vs baseline: 1.0749x; 1.0010x over previous
#include <cuda_runtime.h>

// out[i] = cos(x[i,0] + w0), x: [N,2] float32 interleaved, N = 16777216 (2^24).
// DRAM-wall kernel (25.9us, 78.5% DRAM, issue=13%). R16: identical warp->data
// mapping to the best kernel (warp-contiguous MLP=4, __cosf, .cs stores) with
// 128-thread CTAs (16384 blocks, 16 CTAs/SM) for finer tail-wave granularity —
// the 8192-CTA launch has a 92%-full final wave; halving CTA size smooths it.

__global__ void __launch_bounds__(128)
hybrid_qnn_cos_kernel(const float4* __restrict__ x4,   // N/2 float4s (each = 2 samples)
                      const float* __restrict__ w,
                      float2* __restrict__ out2)       // N/2 float2s
{
    const float w0 = __ldg(w);

    int t = blockIdx.x * blockDim.x + threadIdx.x;
    int warp = t >> 5;
    int lane = t & 31;
    size_t base = (size_t)warp * 128 + lane;

    // 4 independent, warp-coalesced 128B loads (MLP=4, 4 lines per instruction).
    float4 a = __ldg(x4 + base);
    float4 b = __ldg(x4 + base + 32);
    float4 c = __ldg(x4 + base + 64);
    float4 d = __ldg(x4 + base + 96);

    float2 oa = make_float2(__cosf(a.x + w0), __cosf(a.z + w0));
    float2 ob = make_float2(__cosf(b.x + w0), __cosf(b.z + w0));
    float2 oc = make_float2(__cosf(c.x + w0), __cosf(c.z + w0));
    float2 od = make_float2(__cosf(d.x + w0), __cosf(d.z + w0));

    // 4 warp-coalesced 256B streaming stores.
    __stcs(out2 + base,      oa);
    __stcs(out2 + base + 32, ob);
    __stcs(out2 + base + 64, oc);
    __stcs(out2 + base + 96, od);
}

extern "C" void kernel_launch(void* const* d_in, const int* in_sizes, int n_in,
                              void* d_out, int out_size)
{
    const float4* x4 = (const float4*)d_in[0];   // x: [N,2] float32
    const float*  w  = (const float*)d_in[1];    // weights: [2] float32
    float2* out2 = (float2*)d_out;

    int n = in_sizes[0] / 2;        // N samples (2^24)
    int n_x4 = n / 2;               // float4s in x (2^23)
    int n_thread = n_x4 / 4;        // 4 float4s (8 samples) per thread (2^21)

    const int threads = 128;
    int blocks = n_thread / threads;   // 16384 blocks, exact

    hybrid_qnn_cos_kernel<<<blocks, threads>>>(x4, w, out2);
}